// round 14
// baseline (speedup 1.0000x reference)
#include <cuda_runtime.h>
#include <math.h>

#define NN 256
#define BB 1024
#define NJOB 1025
#define NB 32
#define NPAN 8
#define NCHUNK 4
#define PSTR 36
#define SLSTR 132
#define SUSTR 68
#define SMEMF (NB * SLSTR + NB * SUSTR)   // 6400 floats = 25.6 KB

typedef unsigned long long ull;

// ---- device globals (no allocation allowed anywhere) ----
__device__ float2 g_T2[2][NN * NN];              // per-xi planes: (t_xj0, t_xj1)
__device__ float  g_Ws[NN * NN];                 // symmetric sigmoid(W), zero diag
__device__ float2 g_logV[NN];                    // log V[j,0], log V[j,1]
__device__ float  g_A[(size_t)NJOB * NN * NN];   // 268.7 MB LU scratch
__device__ float4 g_L4[(size_t)NJOB * 2048];     // 33.6 MB: -L21 col-major per job
__device__ float  g_ldp[NJOB * NPAN];            // per-panel pivot-log sums
__device__ float  g_logPr[NJOB];

__device__ __forceinline__ float sigm(float z) { return 1.0f / (1.0f + expf(-z)); }
__device__ __forceinline__ float clip01(float v) { return fminf(fmaxf(v, 0.0f), 1.0f); }

__device__ __forceinline__ ull splat2(float x) {
    ull r;
    asm("mov.b64 %0, {%1, %1};" : "=l"(r) : "f"(x));
    return r;
}
__device__ __forceinline__ void ffma2(ull& d, ull a, ull b) {
    asm("fma.rn.f32x2 %0, %1, %2, %0;" : "+l"(d) : "l"(a), "l"(b));
}

// ============================================================================
// Kernel 1: batch-independent precompute of T planes, Ws, logV
// ============================================================================
__global__ void precompute_kernel(const float* __restrict__ W,
                                  const float* __restrict__ lam,
                                  const float* __restrict__ Vc) {
    int i = blockIdx.x, j = threadIdx.x;
    float vi0 = sigm(Vc[2 * i]), vi1 = sigm(Vc[2 * i + 1]);
    float si = vi0 + vi1; vi0 /= si; vi1 /= si;
    float vj0 = sigm(Vc[2 * j]), vj1 = sigm(Vc[2 * j + 1]);
    float sj = vj0 + vj1; vj0 /= sj; vj1 /= sj;

    float ws;
    if (i > j)      ws = sigm(W[i * NN + j]);
    else if (i < j) ws = sigm(W[j * NN + i]);
    else            ws = 0.0f;
    g_Ws[i * NN + j] = ws;

    float t00 = 0.f, t01 = 0.f, t10 = 0.f, t11 = 0.f;
    if (i != j) {
        float lower = fmaxf(1e-7f, vi0 + vj0 - 1.0f);
        float upper = fminf(vi0, vj0);
        float sg = sigm(lam[i * NN + j]);
        float P00 = lower + sg * (upper - lower);
        float P01 = vi0 - P00;
        float P10 = vj0 - P00;
        float P11 = 1.0f - vi0 - vj0 + P00;
        P00 = clip01(P00); P01 = clip01(P01); P10 = clip01(P10); P11 = clip01(P11);
        t00 = ws * P00 / (vi0 * vj0);
        t01 = ws * P01 / (vi0 * vj1);
        t10 = ws * P10 / (vi1 * vj0);
        t11 = ws * P11 / (vi1 * vj1);
    }
    g_T2[0][i * NN + j] = make_float2(t00, t01);
    g_T2[1][i * NN + j] = make_float2(t10, t11);
    if (i == 0) g_logV[j] = make_float2(logf(vj0), logf(vj1));
}

// ============================================================================
// Kernel 2: build M into g_A (1025 CTAs), plus logPr
// ============================================================================
__global__ void __launch_bounds__(256) build_kernel(const int* __restrict__ x) {
    const int job  = blockIdx.x;
    const int tid  = threadIdx.x;
    const int lane = tid & 31;
    const int wid  = tid >> 5;
    const bool isL0 = (job == NJOB - 1);

    __shared__ int   xs[256];
    __shared__ float sW[8];

    float* __restrict__ A = g_A + (size_t)job * (NN * NN);

    if (!isL0) xs[tid] = x[job * NN + tid];
    __syncthreads();

    if (!isL0) {
        float2 lv2 = g_logV[tid];
        float lv = xs[tid] ? lv2.y : lv2.x;
#pragma unroll
        for (int o = 16; o; o >>= 1) lv += __shfl_xor_sync(0xffffffffu, lv, o);
        if (lane == 0) sW[wid] = lv;
    }

    for (int io = wid; io < NN; io += 8) {
        if (io == 255) {
#pragma unroll
            for (int c = 0; c < 8; c++) {
                int j = c * 32 + lane;
                A[255 * NN + j] = (j == 255) ? 1.0f : 0.0f;
            }
        } else {
            int i = io + 1;
            float acc = 0.0f;
            if (!isL0) {
                const float2* Trow = &g_T2[xs[i]][i * NN];
#pragma unroll
                for (int c = 0; c < 8; c++) {
                    int j = c * 32 + lane;
                    float2 t = Trow[j];
                    float v = xs[j] ? t.y : t.x;
                    acc += v;
                    if (j >= 1 && j != i) A[io * NN + (j - 1)] = -v;
                }
            } else {
#pragma unroll
                for (int c = 0; c < 8; c++) {
                    int j = c * 32 + lane;
                    float v = g_Ws[i * NN + j];
                    acc += v;
                    if (j >= 1 && j != i) A[io * NN + (j - 1)] = -v;
                }
            }
#pragma unroll
            for (int o = 16; o; o >>= 1) acc += __shfl_xor_sync(0xffffffffu, acc, o);
            if (lane == 0)  A[io * NN + io]  = acc;
            if (lane == 31) A[io * NN + 255] = 0.0f;
        }
    }
    __syncthreads();

    if (tid == 0 && !isL0) {
        float lp = 0.0f;
#pragma unroll
        for (int q = 0; q < 8; q++) lp += sW[q];
        g_logPr[job] = lp;
    }
}

// ============================================================================
// Fused slot dispatch: each launch carries up to NCHUNK segments, each either
// a panel(p) over a job chunk or a gemm(p) over a job chunk.
// ============================================================================
struct Dispatch {
    int n;
    int type[NCHUNK];    // 0 = panel, 1 = gemm
    int p[NCHUNK];
    int jb[NCHUNK];
    int start[NCHUNK];   // CTA range start
    int tiles[NCHUNK];   // gemm: tiles per job
    int ntc[NCHUNK];     // gemm: col-tiles
};

__device__ __forceinline__ void panel_body(int p, int job, float* smem) {
    const int tid  = threadIdx.x;
    const int lane = tid & 31;
    const int wid  = tid >> 5;
    const int k = p * NB;
    const int m = NN - k;
    const int kb = k + NB;
    const int ncols = NN - kb;

    float* sU11 = smem;                    // U11 rows, zero on/below diag
    float* sLc  = smem + NB * PSTR;        // -L11 columns, zero on/above diag
    float* sInv = smem + 2 * NB * PSTR;    // pivot reciprocals

    float* __restrict__ A = g_A + (size_t)job * (NN * NN);
    float* __restrict__ L = (float*)(g_L4 + (size_t)job * 2048);

    float reg[NB];
    if (tid < m) {
        const float4* ap = (const float4*)(A + (size_t)(k + tid) * NN + k);
#pragma unroll
        for (int q = 0; q < 8; q++) {
            float4 v = ap[q];
            reg[4 * q] = v.x; reg[4 * q + 1] = v.y;
            reg[4 * q + 2] = v.z; reg[4 * q + 3] = v.w;
        }
    }

    if (wid == 0) {
#pragma unroll
        for (int t = 0; t < NB; t++) {
            float bc[NB];
#pragma unroll
            for (int c = t; c < NB; c++)
                bc[c] = __shfl_sync(0xffffffffu, reg[c], t);
            if (lane > t) {
                float l = __fdividef(reg[t], bc[t]);
                reg[t] = l;
#pragma unroll
                for (int c = t + 1; c < NB; c++)
                    reg[c] = fmaf(-l, bc[c], reg[c]);
            }
        }
        float my_inv = 1.0f / reg[lane];
        sInv[lane] = my_inv;
#pragma unroll
        for (int c = 0; c < NB; c++)
            sU11[lane * PSTR + c] = (c > lane) ? reg[c] : 0.0f;
#pragma unroll
        for (int t = 0; t < NB; t++)
            sLc[t * PSTR + lane] = (t < lane) ? -reg[t] : 0.0f;

        float lv = -logf(fabsf(my_inv));
#pragma unroll
        for (int o = 16; o; o >>= 1) lv += __shfl_xor_sync(0xffffffffu, lv, o);
        if (lane == 0) g_ldp[job * NPAN + p] = lv;
    }
    __syncthreads();

    // row-TRSM: L21 = A21 U11^-1; store -L21 col-major into g_L
    if (tid >= NB && tid < m) {
#pragma unroll
        for (int s = 0; s < NB; s++) {
            float l = reg[s] * sInv[s];
            reg[s] = l;
#pragma unroll
            for (int q = 0; q < 8; q++) {
                float4 uu = *(const float4*)&sU11[s * PSTR + 4 * q];
                reg[4 * q]     = fmaf(-l, uu.x, reg[4 * q]);
                reg[4 * q + 1] = fmaf(-l, uu.y, reg[4 * q + 1]);
                reg[4 * q + 2] = fmaf(-l, uu.z, reg[4 * q + 2]);
                reg[4 * q + 3] = fmaf(-l, uu.w, reg[4 * q + 3]);
            }
        }
        const int row = k + tid;
#pragma unroll
        for (int c = 0; c < NB; c++)
            L[c * NN + row] = -reg[c];
    }

    // column-TRSM: U12 = L11^-1 A12, per-thread global column
    if (tid < ncols) {
        const int c = kb + tid;
        float u[NB];
#pragma unroll
        for (int r = 0; r < NB; r++) u[r] = A[(size_t)(k + r) * NN + c];
#pragma unroll
        for (int t = 0; t < NB - 1; t++) {
            float ut = u[t];
#pragma unroll
            for (int q = 0; q < 8; q++) {
                float4 pv = *(const float4*)&sLc[t * PSTR + 4 * q];
                u[4 * q]     = fmaf(pv.x, ut, u[4 * q]);
                u[4 * q + 1] = fmaf(pv.y, ut, u[4 * q + 1]);
                u[4 * q + 2] = fmaf(pv.z, ut, u[4 * q + 2]);
                u[4 * q + 3] = fmaf(pv.w, ut, u[4 * q + 3]);
            }
        }
#pragma unroll
        for (int r = 0; r < NB; r++) A[(size_t)(k + r) * NN + c] = u[r];
    }
}

__device__ __forceinline__ void gemm_body(int p, int job, int by, int bx,
                                          float* smem) {
    const int k = p * NB;
    const int kb = k + NB;
    const int rowbase = kb + by * 128;
    const int colbase = kb + bx * 64;
    const int tid = threadIdx.x;

    float* sL = smem;                 // [kk][r_local 0..127]
    float* sU = smem + NB * SLSTR;    // [kk][c_local 0..63]

    float* __restrict__ A = g_A + (size_t)job * (NN * NN);
    const float* __restrict__ L = (const float*)(g_L4 + (size_t)job * 2048);

#pragma unroll
    for (int it = 0; it < 4; it++) {
        int idx = it * 256 + tid;
        int kk = idx >> 5, p4 = (idx & 31) * 4;
        int row = rowbase + p4;
        float4 v = make_float4(0.f, 0.f, 0.f, 0.f);
        if (row < NN) v = *(const float4*)&L[kk * NN + row];
        *(float4*)&sL[kk * SLSTR + p4] = v;
    }
#pragma unroll
    for (int it = 0; it < 2; it++) {
        int idx = it * 256 + tid;
        int kk = idx >> 4, p4 = (idx & 15) * 4;
        int col = colbase + p4;
        float4 v = make_float4(0.f, 0.f, 0.f, 0.f);
        if (col < NN) v = *(const float4*)&A[(size_t)(k + kk) * NN + col];
        *(float4*)&sU[kk * SUSTR + p4] = v;
    }
    __syncthreads();

    const int tr = tid >> 4, tc = tid & 15;
    const int rl = 8 * tr, cl = 4 * tc;
    const int r0 = rowbase + rl;
    const int c0 = colbase + cl;
    if (c0 >= NN || r0 >= NN) return;

    ulonglong2 acc[8];
#pragma unroll
    for (int i = 0; i < 8; i++) {
        if (r0 + i < NN) acc[i] = *(ulonglong2*)(A + (size_t)(r0 + i) * NN + c0);
        else             acc[i] = make_ulonglong2(0ull, 0ull);
    }

#pragma unroll 4
    for (int kk = 0; kk < NB; kk++) {
        float4 lfa = *(const float4*)&sL[kk * SLSTR + rl];
        float4 lfb = *(const float4*)&sL[kk * SLSTR + rl + 4];
        ulonglong2 uv = *(const ulonglong2*)&sU[kk * SUSTR + cl];
        ull l0 = splat2(lfa.x), l1 = splat2(lfa.y);
        ull l2 = splat2(lfa.z), l3 = splat2(lfa.w);
        ull l4 = splat2(lfb.x), l5 = splat2(lfb.y);
        ull l6 = splat2(lfb.z), l7 = splat2(lfb.w);
        ffma2(acc[0].x, l0, uv.x); ffma2(acc[0].y, l0, uv.y);
        ffma2(acc[1].x, l1, uv.x); ffma2(acc[1].y, l1, uv.y);
        ffma2(acc[2].x, l2, uv.x); ffma2(acc[2].y, l2, uv.y);
        ffma2(acc[3].x, l3, uv.x); ffma2(acc[3].y, l3, uv.y);
        ffma2(acc[4].x, l4, uv.x); ffma2(acc[4].y, l4, uv.y);
        ffma2(acc[5].x, l5, uv.x); ffma2(acc[5].y, l5, uv.y);
        ffma2(acc[6].x, l6, uv.x); ffma2(acc[6].y, l6, uv.y);
        ffma2(acc[7].x, l7, uv.x); ffma2(acc[7].y, l7, uv.y);
    }

#pragma unroll
    for (int i = 0; i < 8; i++) {
        if (r0 + i < NN) *(ulonglong2*)(A + (size_t)(r0 + i) * NN + c0) = acc[i];
    }
}

__global__ void __launch_bounds__(256, 2) step_kernel(Dispatch d) {
    __shared__ float smem[SMEMF];
    const int b = blockIdx.x;

    int s = 0;
#pragma unroll
    for (int i = 1; i < NCHUNK; i++)
        if (i < d.n && b >= d.start[i]) s = i;

    const int local = b - d.start[s];
    if (d.type[s] == 0) {
        panel_body(d.p[s], d.jb[s] + local, smem);
    } else {
        const int tiles = d.tiles[s];
        const int job = d.jb[s] + local / tiles;
        const int rem = local % tiles;
        gemm_body(d.p[s], job, rem / d.ntc[s], rem % d.ntc[s], smem);
    }
}

// ============================================================================
// Kernel 5: finalize
// ============================================================================
__global__ void finalize_kernel(float* __restrict__ out) {
    int i = blockIdx.x * 256 + threadIdx.x;
    if (i < BB) {
        float ld = 0.0f, ld0 = 0.0f;
#pragma unroll
        for (int q = 0; q < NPAN; q++) {
            ld  += g_ldp[i * NPAN + q];
            ld0 += g_ldp[(NJOB - 1) * NPAN + q];
        }
        out[i] = g_logPr[i] + ld - ld0;
    }
}

extern "C" void kernel_launch(void* const* d_in, const int* in_sizes, int n_in,
                              void* d_out, int out_size) {
    const float* W   = (const float*)d_in[0];
    const float* lam = (const float*)d_in[1];
    const float* Vc  = (const float*)d_in[2];
    const int*   x   = (const int*)d_in[3];
    float* out = (float*)d_out;

    // chunk boundaries: 256,256,256,257 (job 1024 = L0 rides in the last chunk)
    int base[NCHUNK + 1];
    for (int c = 0; c < NCHUNK; c++) base[c] = c * 256;
    base[NCHUNK] = NJOB;

    precompute_kernel<<<NN, NN>>>(W, lam, Vc);
    build_kernel<<<NJOB, 256>>>(x);

    // slot-scheduled pipeline: chunk c's item sequence P0,G0,P1,...,G6,P7
    // (15 items) offset by c slots. One fused launch per slot.
    const int NITEM = 2 * NPAN - 1;           // 15
    for (int t = 0; t < NITEM + NCHUNK - 1; t++) {
        Dispatch d;
        d.n = 0;
        int cta = 0;
        for (int c = 0; c < NCHUNK; c++) {
            int item = t - c;
            if (item < 0 || item >= NITEM) continue;
            int jb = base[c], nj = base[c + 1] - base[c];
            int p = item >> 1;
            if ((item & 1) == 0) {            // panel p
                d.type[d.n] = 0; d.p[d.n] = p; d.jb[d.n] = jb;
                d.start[d.n] = cta; d.tiles[d.n] = 1; d.ntc[d.n] = 1;
                cta += nj; d.n++;
            } else {                           // gemm p (p <= 6)
                int ncols = NN - (p * NB + NB);
                int ntr = (ncols + 127) / 128;
                int ntc = (ncols + 63) / 64;
                d.type[d.n] = 1; d.p[d.n] = p; d.jb[d.n] = jb;
                d.start[d.n] = cta; d.tiles[d.n] = ntr * ntc; d.ntc[d.n] = ntc;
                cta += ntr * ntc * nj; d.n++;
            }
        }
        if (d.n > 0) step_kernel<<<cta, 256>>>(d);
    }

    finalize_kernel<<<4, 256>>>(out);
}

// round 15
// speedup vs baseline: 1.2500x; 1.2500x over previous
#include <cuda_runtime.h>
#include <math.h>

#define NN 256
#define BB 1024
#define NJOB 1025
#define NB 32
#define NPAN 8
#define PSTR 36
#define SLSTR 132
#define SUSTR 68

typedef unsigned long long ull;

// ---- device globals (no allocation allowed anywhere) ----
__device__ float2 g_T2[2][NN * NN];              // per-xi planes: (t_xj0, t_xj1)
__device__ float  g_Ws[NN * NN];                 // symmetric sigmoid(W), zero diag
__device__ float2 g_logV[NN];                    // log V[j,0], log V[j,1]
__device__ float  g_A[(size_t)NJOB * NN * NN];   // 268.7 MB LU scratch
__device__ float4 g_L4[(size_t)NJOB * 2048];     // 33.6 MB: -L21 col-major per job
__device__ float  g_ldp[NJOB * NPAN];            // per-panel pivot-log sums
__device__ float  g_logPr[NJOB];

__device__ __forceinline__ float sigm(float z) { return 1.0f / (1.0f + expf(-z)); }
__device__ __forceinline__ float clip01(float v) { return fminf(fmaxf(v, 0.0f), 1.0f); }

__device__ __forceinline__ ull splat2(float x) {
    ull r;
    asm("mov.b64 %0, {%1, %1};" : "=l"(r) : "f"(x));
    return r;
}
__device__ __forceinline__ void ffma2(ull& d, ull a, ull b) {
    asm("fma.rn.f32x2 %0, %1, %2, %0;" : "+l"(d) : "l"(a), "l"(b));
}

// ============================================================================
// Kernel 1: batch-independent precompute of T planes, Ws, logV
// ============================================================================
__global__ void precompute_kernel(const float* __restrict__ W,
                                  const float* __restrict__ lam,
                                  const float* __restrict__ Vc) {
    int i = blockIdx.x, j = threadIdx.x;
    float vi0 = sigm(Vc[2 * i]), vi1 = sigm(Vc[2 * i + 1]);
    float si = vi0 + vi1; vi0 /= si; vi1 /= si;
    float vj0 = sigm(Vc[2 * j]), vj1 = sigm(Vc[2 * j + 1]);
    float sj = vj0 + vj1; vj0 /= sj; vj1 /= sj;

    float ws;
    if (i > j)      ws = sigm(W[i * NN + j]);
    else if (i < j) ws = sigm(W[j * NN + i]);
    else            ws = 0.0f;
    g_Ws[i * NN + j] = ws;

    float t00 = 0.f, t01 = 0.f, t10 = 0.f, t11 = 0.f;
    if (i != j) {
        float lower = fmaxf(1e-7f, vi0 + vj0 - 1.0f);
        float upper = fminf(vi0, vj0);
        float sg = sigm(lam[i * NN + j]);
        float P00 = lower + sg * (upper - lower);
        float P01 = vi0 - P00;
        float P10 = vj0 - P00;
        float P11 = 1.0f - vi0 - vj0 + P00;
        P00 = clip01(P00); P01 = clip01(P01); P10 = clip01(P10); P11 = clip01(P11);
        t00 = ws * P00 / (vi0 * vj0);
        t01 = ws * P01 / (vi0 * vj1);
        t10 = ws * P10 / (vi1 * vj0);
        t11 = ws * P11 / (vi1 * vj1);
    }
    g_T2[0][i * NN + j] = make_float2(t00, t01);
    g_T2[1][i * NN + j] = make_float2(t10, t11);
    if (i == 0) g_logV[j] = make_float2(logf(vj0), logf(vj1));
}

// ============================================================================
// Kernel 2: build M into g_A (1025 CTAs), plus logPr
// ============================================================================
__global__ void __launch_bounds__(256) build_kernel(const int* __restrict__ x) {
    const int job  = blockIdx.x;
    const int tid  = threadIdx.x;
    const int lane = tid & 31;
    const int wid  = tid >> 5;
    const bool isL0 = (job == NJOB - 1);

    __shared__ int   xs[256];
    __shared__ float sW[8];

    float* __restrict__ A = g_A + (size_t)job * (NN * NN);

    if (!isL0) xs[tid] = x[job * NN + tid];
    __syncthreads();

    if (!isL0) {
        float2 lv2 = g_logV[tid];
        float lv = xs[tid] ? lv2.y : lv2.x;
#pragma unroll
        for (int o = 16; o; o >>= 1) lv += __shfl_xor_sync(0xffffffffu, lv, o);
        if (lane == 0) sW[wid] = lv;
    }

    for (int io = wid; io < NN; io += 8) {
        if (io == 255) {
#pragma unroll
            for (int c = 0; c < 8; c++) {
                int j = c * 32 + lane;
                A[255 * NN + j] = (j == 255) ? 1.0f : 0.0f;
            }
        } else {
            int i = io + 1;
            float acc = 0.0f;
            if (!isL0) {
                const float2* Trow = &g_T2[xs[i]][i * NN];
#pragma unroll
                for (int c = 0; c < 8; c++) {
                    int j = c * 32 + lane;
                    float2 t = Trow[j];
                    float v = xs[j] ? t.y : t.x;
                    acc += v;
                    if (j >= 1 && j != i) A[io * NN + (j - 1)] = -v;
                }
            } else {
#pragma unroll
                for (int c = 0; c < 8; c++) {
                    int j = c * 32 + lane;
                    float v = g_Ws[i * NN + j];
                    acc += v;
                    if (j >= 1 && j != i) A[io * NN + (j - 1)] = -v;
                }
            }
#pragma unroll
            for (int o = 16; o; o >>= 1) acc += __shfl_xor_sync(0xffffffffu, acc, o);
            if (lane == 0)  A[io * NN + io]  = acc;
            if (lane == 31) A[io * NN + 255] = 0.0f;
        }
    }
    __syncthreads();

    if (tid == 0 && !isL0) {
        float lp = 0.0f;
#pragma unroll
        for (int q = 0; q < 8; q++) lp += sW[q];
        g_logPr[job] = lp;
    }
}

// ============================================================================
// Kernel 3: panel p — shuffle-LU of diagonal block + row-TRSM (L21, written
// negated+transposed into g_L) + column-TRSM (U12, in-place in A).
// 3 CTAs/SM (85-reg cap; live-reg peak ~70, no spill expected).
// ============================================================================
__global__ void __launch_bounds__(256, 3) panel_kernel(int p) {
    const int job  = blockIdx.x;
    const int tid  = threadIdx.x;
    const int lane = tid & 31;
    const int wid  = tid >> 5;
    const int k = p * NB;
    const int m = NN - k;
    const int kb = k + NB;
    const int ncols = NN - kb;

    __shared__ float sU11[NB * PSTR];   // U11 rows, zero on/below diag
    __shared__ float sLc[NB * PSTR];    // -L11 columns, zero on/above diag
    __shared__ float sInv[NB];          // pivot reciprocals

    float* __restrict__ A = g_A + (size_t)job * (NN * NN);
    float* __restrict__ L = (float*)(g_L4 + (size_t)job * 2048);

    // load panel rows (cols k..k+31 of row k+tid) into registers
    float reg[NB];
    if (tid < m) {
        const float4* ap = (const float4*)(A + (size_t)(k + tid) * NN + k);
#pragma unroll
        for (int q = 0; q < 8; q++) {
            float4 v = ap[q];
            reg[4 * q] = v.x; reg[4 * q + 1] = v.y;
            reg[4 * q + 2] = v.z; reg[4 * q + 3] = v.w;
        }
    }

    if (wid == 0) {
        // shuffle-LU of the 32x32 diagonal block (lane r owns row k+r)
#pragma unroll
        for (int t = 0; t < NB; t++) {
            float bc[NB];
#pragma unroll
            for (int c = t; c < NB; c++)
                bc[c] = __shfl_sync(0xffffffffu, reg[c], t);
            if (lane > t) {
                float l = __fdividef(reg[t], bc[t]);
                reg[t] = l;
#pragma unroll
                for (int c = t + 1; c < NB; c++)
                    reg[c] = fmaf(-l, bc[c], reg[c]);
            }
        }
        float my_inv = 1.0f / reg[lane];
        sInv[lane] = my_inv;
#pragma unroll
        for (int c = 0; c < NB; c++)
            sU11[lane * PSTR + c] = (c > lane) ? reg[c] : 0.0f;
#pragma unroll
        for (int t = 0; t < NB; t++)
            sLc[t * PSTR + lane] = (t < lane) ? -reg[t] : 0.0f;

        // pivot logs
        float lv = -logf(fabsf(my_inv));
#pragma unroll
        for (int o = 16; o; o >>= 1) lv += __shfl_xor_sync(0xffffffffu, lv, o);
        if (lane == 0) g_ldp[job * NPAN + p] = lv;
    }
    __syncthreads();

    // row-TRSM: L21 = A21 U11^-1 (per-thread row, no barriers),
    // store -L21 col-major into g_L (coalesced across threads)
    if (tid >= NB && tid < m) {
#pragma unroll
        for (int s = 0; s < NB; s++) {
            float l = reg[s] * sInv[s];
            reg[s] = l;
#pragma unroll
            for (int q = 0; q < 8; q++) {
                float4 uu = *(const float4*)&sU11[s * PSTR + 4 * q];
                reg[4 * q]     = fmaf(-l, uu.x, reg[4 * q]);
                reg[4 * q + 1] = fmaf(-l, uu.y, reg[4 * q + 1]);
                reg[4 * q + 2] = fmaf(-l, uu.z, reg[4 * q + 2]);
                reg[4 * q + 3] = fmaf(-l, uu.w, reg[4 * q + 3]);
            }
        }
        const int row = k + tid;
#pragma unroll
        for (int c = 0; c < NB; c++)
            L[c * NN + row] = -reg[c];
    }

    // column-TRSM: U12 = L11^-1 A12, per-thread global column (coalesced)
    if (tid < ncols) {
        const int c = kb + tid;
        float u[NB];
#pragma unroll
        for (int r = 0; r < NB; r++) u[r] = A[(size_t)(k + r) * NN + c];
#pragma unroll
        for (int t = 0; t < NB - 1; t++) {
            float ut = u[t];
#pragma unroll
            for (int q = 0; q < 8; q++) {
                float4 pv = *(const float4*)&sLc[t * PSTR + 4 * q];
                u[4 * q]     = fmaf(pv.x, ut, u[4 * q]);
                u[4 * q + 1] = fmaf(pv.y, ut, u[4 * q + 1]);
                u[4 * q + 2] = fmaf(pv.z, ut, u[4 * q + 2]);
                u[4 * q + 3] = fmaf(pv.w, ut, u[4 * q + 3]);
            }
        }
#pragma unroll
        for (int r = 0; r < NB; r++) A[(size_t)(k + r) * NN + c] = u[r];
    }
}

// ============================================================================
// Kernel 4: trailing GEMM for panel p: A22 += (-L21) * U12.
// grid (ntc, ntr, NJOB): 128x64 tile per CTA, 8 rows x 4 cols per thread.
// ============================================================================
__global__ void __launch_bounds__(256, 3) gemm_kernel(int p) {
    const int k = p * NB;
    const int kb = k + NB;
    const int job = blockIdx.z;
    const int rowbase = kb + blockIdx.y * 128;
    const int colbase = kb + blockIdx.x * 64;
    const int tid = threadIdx.x;

    __shared__ float sL[NB * SLSTR];  // [kk][r_local 0..127]
    __shared__ float sU[NB * SUSTR];  // [kk][c_local 0..63]

    float* __restrict__ A = g_A + (size_t)job * (NN * NN);
    const float* __restrict__ L = (const float*)(g_L4 + (size_t)job * 2048);

#pragma unroll
    for (int it = 0; it < 4; it++) {
        int idx = it * 256 + tid;
        int kk = idx >> 5, p4 = (idx & 31) * 4;
        int row = rowbase + p4;
        float4 v = make_float4(0.f, 0.f, 0.f, 0.f);
        if (row < NN) v = *(const float4*)&L[kk * NN + row];
        *(float4*)&sL[kk * SLSTR + p4] = v;
    }
#pragma unroll
    for (int it = 0; it < 2; it++) {
        int idx = it * 256 + tid;
        int kk = idx >> 4, p4 = (idx & 15) * 4;
        int col = colbase + p4;
        float4 v = make_float4(0.f, 0.f, 0.f, 0.f);
        if (col < NN) v = *(const float4*)&A[(size_t)(k + kk) * NN + col];
        *(float4*)&sU[kk * SUSTR + p4] = v;
    }
    __syncthreads();

    const int tr = tid >> 4, tc = tid & 15;
    const int rl = 8 * tr, cl = 4 * tc;
    const int r0 = rowbase + rl;
    const int c0 = colbase + cl;
    if (c0 >= NN || r0 >= NN) return;

    ulonglong2 acc[8];
#pragma unroll
    for (int i = 0; i < 8; i++) {
        if (r0 + i < NN) acc[i] = *(ulonglong2*)(A + (size_t)(r0 + i) * NN + c0);
        else             acc[i] = make_ulonglong2(0ull, 0ull);
    }

#pragma unroll 4
    for (int kk = 0; kk < NB; kk++) {
        float4 lfa = *(const float4*)&sL[kk * SLSTR + rl];
        float4 lfb = *(const float4*)&sL[kk * SLSTR + rl + 4];
        ulonglong2 uv = *(const ulonglong2*)&sU[kk * SUSTR + cl];
        ull l0 = splat2(lfa.x), l1 = splat2(lfa.y);
        ull l2 = splat2(lfa.z), l3 = splat2(lfa.w);
        ull l4 = splat2(lfb.x), l5 = splat2(lfb.y);
        ull l6 = splat2(lfb.z), l7 = splat2(lfb.w);
        ffma2(acc[0].x, l0, uv.x); ffma2(acc[0].y, l0, uv.y);
        ffma2(acc[1].x, l1, uv.x); ffma2(acc[1].y, l1, uv.y);
        ffma2(acc[2].x, l2, uv.x); ffma2(acc[2].y, l2, uv.y);
        ffma2(acc[3].x, l3, uv.x); ffma2(acc[3].y, l3, uv.y);
        ffma2(acc[4].x, l4, uv.x); ffma2(acc[4].y, l4, uv.y);
        ffma2(acc[5].x, l5, uv.x); ffma2(acc[5].y, l5, uv.y);
        ffma2(acc[6].x, l6, uv.x); ffma2(acc[6].y, l6, uv.y);
        ffma2(acc[7].x, l7, uv.x); ffma2(acc[7].y, l7, uv.y);
    }

#pragma unroll
    for (int i = 0; i < 8; i++) {
        if (r0 + i < NN) *(ulonglong2*)(A + (size_t)(r0 + i) * NN + c0) = acc[i];
    }
}

// ============================================================================
// Kernel 5: finalize
// ============================================================================
__global__ void finalize_kernel(float* __restrict__ out) {
    int i = blockIdx.x * 256 + threadIdx.x;
    if (i < BB) {
        float ld = 0.0f, ld0 = 0.0f;
#pragma unroll
        for (int q = 0; q < NPAN; q++) {
            ld  += g_ldp[i * NPAN + q];
            ld0 += g_ldp[(NJOB - 1) * NPAN + q];
        }
        out[i] = g_logPr[i] + ld - ld0;
    }
}

extern "C" void kernel_launch(void* const* d_in, const int* in_sizes, int n_in,
                              void* d_out, int out_size) {
    const float* W   = (const float*)d_in[0];
    const float* lam = (const float*)d_in[1];
    const float* Vc  = (const float*)d_in[2];
    const int*   x   = (const int*)d_in[3];
    float* out = (float*)d_out;

    precompute_kernel<<<NN, NN>>>(W, lam, Vc);
    build_kernel<<<NJOB, 256>>>(x);
    for (int p = 0; p < NPAN; p++) {
        panel_kernel<<<NJOB, 256>>>(p);
        int ncols = NN - (p * NB + NB);
        if (ncols > 0) {
            int ntr = (ncols + 127) / 128;
            int ntc = (ncols + 63) / 64;
            gemm_kernel<<<dim3(ntc, ntr, NJOB), 256>>>(p);
        }
    }
    finalize_kernel<<<4, 256>>>(out);
}

// round 16
// speedup vs baseline: 1.2834x; 1.0267x over previous
#include <cuda_runtime.h>
#include <math.h>

#define NN 256
#define BB 1024
#define NJOB 1025
#define NB 32
#define NPAN 8
#define PSTR 36
#define SLSTR 132
#define SUSTR 68

typedef unsigned long long ull;

// ---- device globals (no allocation allowed anywhere) ----
__device__ float2 g_T2[2][NN * NN];              // per-xi planes: (t_xj0, t_xj1)
__device__ float  g_Ws[NN * NN];                 // symmetric sigmoid(W), zero diag
__device__ float2 g_logV[NN];                    // log V[j,0], log V[j,1]
__device__ float  g_A[(size_t)NJOB * NN * NN];   // 268.7 MB LU scratch
__device__ float4 g_L4[(size_t)NJOB * 2048];     // 33.6 MB: -L21 col-major per job
__device__ float  g_ldp[NJOB * NPAN];            // per-panel pivot-log sums
__device__ float  g_logPr[NJOB];

__device__ __forceinline__ float sigm(float z) { return 1.0f / (1.0f + expf(-z)); }
__device__ __forceinline__ float clip01(float v) { return fminf(fmaxf(v, 0.0f), 1.0f); }

__device__ __forceinline__ ull splat2(float x) {
    ull r;
    asm("mov.b64 %0, {%1, %1};" : "=l"(r) : "f"(x));
    return r;
}
__device__ __forceinline__ void ffma2(ull& d, ull a, ull b) {
    asm("fma.rn.f32x2 %0, %1, %2, %0;" : "+l"(d) : "l"(a), "l"(b));
}

// ============================================================================
// Kernel 1: batch-independent precompute of T planes, Ws, logV
// ============================================================================
__global__ void precompute_kernel(const float* __restrict__ W,
                                  const float* __restrict__ lam,
                                  const float* __restrict__ Vc) {
    int i = blockIdx.x, j = threadIdx.x;
    float vi0 = sigm(Vc[2 * i]), vi1 = sigm(Vc[2 * i + 1]);
    float si = vi0 + vi1; vi0 /= si; vi1 /= si;
    float vj0 = sigm(Vc[2 * j]), vj1 = sigm(Vc[2 * j + 1]);
    float sj = vj0 + vj1; vj0 /= sj; vj1 /= sj;

    float ws;
    if (i > j)      ws = sigm(W[i * NN + j]);
    else if (i < j) ws = sigm(W[j * NN + i]);
    else            ws = 0.0f;
    g_Ws[i * NN + j] = ws;

    float t00 = 0.f, t01 = 0.f, t10 = 0.f, t11 = 0.f;
    if (i != j) {
        float lower = fmaxf(1e-7f, vi0 + vj0 - 1.0f);
        float upper = fminf(vi0, vj0);
        float sg = sigm(lam[i * NN + j]);
        float P00 = lower + sg * (upper - lower);
        float P01 = vi0 - P00;
        float P10 = vj0 - P00;
        float P11 = 1.0f - vi0 - vj0 + P00;
        P00 = clip01(P00); P01 = clip01(P01); P10 = clip01(P10); P11 = clip01(P11);
        t00 = ws * P00 / (vi0 * vj0);
        t01 = ws * P01 / (vi0 * vj1);
        t10 = ws * P10 / (vi1 * vj0);
        t11 = ws * P11 / (vi1 * vj1);
    }
    g_T2[0][i * NN + j] = make_float2(t00, t01);
    g_T2[1][i * NN + j] = make_float2(t10, t11);
    if (i == 0) g_logV[j] = make_float2(logf(vj0), logf(vj1));
}

// ============================================================================
// Kernel 2: build M into g_A (1025 CTAs), plus logPr
// ============================================================================
__global__ void __launch_bounds__(256) build_kernel(const int* __restrict__ x) {
    const int job  = blockIdx.x;
    const int tid  = threadIdx.x;
    const int lane = tid & 31;
    const int wid  = tid >> 5;
    const bool isL0 = (job == NJOB - 1);

    __shared__ int   xs[256];
    __shared__ float sW[8];

    float* __restrict__ A = g_A + (size_t)job * (NN * NN);

    if (!isL0) xs[tid] = x[job * NN + tid];
    __syncthreads();

    if (!isL0) {
        float2 lv2 = g_logV[tid];
        float lv = xs[tid] ? lv2.y : lv2.x;
#pragma unroll
        for (int o = 16; o; o >>= 1) lv += __shfl_xor_sync(0xffffffffu, lv, o);
        if (lane == 0) sW[wid] = lv;
    }

    for (int io = wid; io < NN; io += 8) {
        if (io == 255) {
#pragma unroll
            for (int c = 0; c < 8; c++) {
                int j = c * 32 + lane;
                A[255 * NN + j] = (j == 255) ? 1.0f : 0.0f;
            }
        } else {
            int i = io + 1;
            float acc = 0.0f;
            if (!isL0) {
                const float2* Trow = &g_T2[xs[i]][i * NN];
#pragma unroll
                for (int c = 0; c < 8; c++) {
                    int j = c * 32 + lane;
                    float2 t = Trow[j];
                    float v = xs[j] ? t.y : t.x;
                    acc += v;
                    if (j >= 1 && j != i) A[io * NN + (j - 1)] = -v;
                }
            } else {
#pragma unroll
                for (int c = 0; c < 8; c++) {
                    int j = c * 32 + lane;
                    float v = g_Ws[i * NN + j];
                    acc += v;
                    if (j >= 1 && j != i) A[io * NN + (j - 1)] = -v;
                }
            }
#pragma unroll
            for (int o = 16; o; o >>= 1) acc += __shfl_xor_sync(0xffffffffu, acc, o);
            if (lane == 0)  A[io * NN + io]  = acc;
            if (lane == 31) A[io * NN + 255] = 0.0f;
        }
    }
    __syncthreads();

    if (tid == 0 && !isL0) {
        float lp = 0.0f;
#pragma unroll
        for (int q = 0; q < 8; q++) lp += sW[q];
        g_logPr[job] = lp;
    }
}

// ============================================================================
// Kernel 3: panel p — PDL secondary: sync (guards reads of gemm p-1 output),
// trigger (certifies gemm p-1 complete for the NEXT launch), then the proven
// shuffle-LU + row-TRSM + column-TRSM body. 3 CTAs/SM.
// ============================================================================
__global__ void __launch_bounds__(256, 3) panel_kernel(int p) {
    cudaGridDependencySynchronize();
    cudaTriggerProgrammaticLaunchCompletion();

    const int job  = blockIdx.x;
    const int tid  = threadIdx.x;
    const int lane = tid & 31;
    const int wid  = tid >> 5;
    const int k = p * NB;
    const int m = NN - k;
    const int kb = k + NB;
    const int ncols = NN - kb;

    __shared__ float sU11[NB * PSTR];   // U11 rows, zero on/below diag
    __shared__ float sLc[NB * PSTR];    // -L11 columns, zero on/above diag
    __shared__ float sInv[NB];          // pivot reciprocals

    float* __restrict__ A = g_A + (size_t)job * (NN * NN);
    float* __restrict__ L = (float*)(g_L4 + (size_t)job * 2048);

    float reg[NB];
    if (tid < m) {
        const float4* ap = (const float4*)(A + (size_t)(k + tid) * NN + k);
#pragma unroll
        for (int q = 0; q < 8; q++) {
            float4 v = ap[q];
            reg[4 * q] = v.x; reg[4 * q + 1] = v.y;
            reg[4 * q + 2] = v.z; reg[4 * q + 3] = v.w;
        }
    }

    if (wid == 0) {
#pragma unroll
        for (int t = 0; t < NB; t++) {
            float bc[NB];
#pragma unroll
            for (int c = t; c < NB; c++)
                bc[c] = __shfl_sync(0xffffffffu, reg[c], t);
            if (lane > t) {
                float l = __fdividef(reg[t], bc[t]);
                reg[t] = l;
#pragma unroll
                for (int c = t + 1; c < NB; c++)
                    reg[c] = fmaf(-l, bc[c], reg[c]);
            }
        }
        float my_inv = 1.0f / reg[lane];
        sInv[lane] = my_inv;
#pragma unroll
        for (int c = 0; c < NB; c++)
            sU11[lane * PSTR + c] = (c > lane) ? reg[c] : 0.0f;
#pragma unroll
        for (int t = 0; t < NB; t++)
            sLc[t * PSTR + lane] = (t < lane) ? -reg[t] : 0.0f;

        float lv = -logf(fabsf(my_inv));
#pragma unroll
        for (int o = 16; o; o >>= 1) lv += __shfl_xor_sync(0xffffffffu, lv, o);
        if (lane == 0) g_ldp[job * NPAN + p] = lv;
    }
    __syncthreads();

    // row-TRSM: L21 = A21 U11^-1; store -L21 col-major into g_L
    if (tid >= NB && tid < m) {
#pragma unroll
        for (int s = 0; s < NB; s++) {
            float l = reg[s] * sInv[s];
            reg[s] = l;
#pragma unroll
            for (int q = 0; q < 8; q++) {
                float4 uu = *(const float4*)&sU11[s * PSTR + 4 * q];
                reg[4 * q]     = fmaf(-l, uu.x, reg[4 * q]);
                reg[4 * q + 1] = fmaf(-l, uu.y, reg[4 * q + 1]);
                reg[4 * q + 2] = fmaf(-l, uu.z, reg[4 * q + 2]);
                reg[4 * q + 3] = fmaf(-l, uu.w, reg[4 * q + 3]);
            }
        }
        const int row = k + tid;
#pragma unroll
        for (int c = 0; c < NB; c++)
            L[c * NN + row] = -reg[c];
    }

    // column-TRSM: U12 = L11^-1 A12, per-thread global column
    if (tid < ncols) {
        const int c = kb + tid;
        float u[NB];
#pragma unroll
        for (int r = 0; r < NB; r++) u[r] = A[(size_t)(k + r) * NN + c];
#pragma unroll
        for (int t = 0; t < NB - 1; t++) {
            float ut = u[t];
#pragma unroll
            for (int q = 0; q < 8; q++) {
                float4 pv = *(const float4*)&sLc[t * PSTR + 4 * q];
                u[4 * q]     = fmaf(pv.x, ut, u[4 * q]);
                u[4 * q + 1] = fmaf(pv.y, ut, u[4 * q + 1]);
                u[4 * q + 2] = fmaf(pv.z, ut, u[4 * q + 2]);
                u[4 * q + 3] = fmaf(pv.w, ut, u[4 * q + 3]);
            }
        }
#pragma unroll
        for (int r = 0; r < NB; r++) A[(size_t)(k + r) * NN + c] = u[r];
    }
}

// ============================================================================
// Kernel 4: trailing GEMM for panel p — PDL secondary of panel p: preloads C
// accumulators (region untouched by panel p; prior writer gemm p-1 is complete
// by panel p's trigger ordering) BEFORE the dependency sync, overlapping its
// DRAM-heavy phase with panel p's latency-bound tail. Then sync, stage, FMA.
// ============================================================================
__global__ void __launch_bounds__(256, 3) gemm_kernel(int p) {
    const int k = p * NB;
    const int kb = k + NB;
    const int job = blockIdx.z;
    const int rowbase = kb + blockIdx.y * 128;
    const int colbase = kb + blockIdx.x * 64;
    const int tid = threadIdx.x;

    __shared__ float sL[NB * SLSTR];  // [kk][r_local 0..127]
    __shared__ float sU[NB * SUSTR];  // [kk][c_local 0..63]

    float* __restrict__ A = g_A + (size_t)job * (NN * NN);
    const float* __restrict__ L = (const float*)(g_L4 + (size_t)job * 2048);

    const int tr = tid >> 4, tc = tid & 15;
    const int rl = 8 * tr, cl = 4 * tc;
    const int r0 = rowbase + rl;
    const int c0 = colbase + cl;
    const bool inb = (c0 < NN) && (r0 < NN);

    // preload C accumulators BEFORE the dependency sync (overlaps panel tail)
    ulonglong2 acc[8];
#pragma unroll
    for (int i = 0; i < 8; i++) {
        if (inb && r0 + i < NN)
            acc[i] = *(ulonglong2*)(A + (size_t)(r0 + i) * NN + c0);
        else
            acc[i] = make_ulonglong2(0ull, 0ull);
    }

    cudaGridDependencySynchronize();
    cudaTriggerProgrammaticLaunchCompletion();

#pragma unroll
    for (int it = 0; it < 4; it++) {
        int idx = it * 256 + tid;
        int kk = idx >> 5, p4 = (idx & 31) * 4;
        int row = rowbase + p4;
        float4 v = make_float4(0.f, 0.f, 0.f, 0.f);
        if (row < NN) v = *(const float4*)&L[kk * NN + row];
        *(float4*)&sL[kk * SLSTR + p4] = v;
    }
#pragma unroll
    for (int it = 0; it < 2; it++) {
        int idx = it * 256 + tid;
        int kk = idx >> 4, p4 = (idx & 15) * 4;
        int col = colbase + p4;
        float4 v = make_float4(0.f, 0.f, 0.f, 0.f);
        if (col < NN) v = *(const float4*)&A[(size_t)(k + kk) * NN + col];
        *(float4*)&sU[kk * SUSTR + p4] = v;
    }
    __syncthreads();

    if (inb) {
#pragma unroll 4
        for (int kk = 0; kk < NB; kk++) {
            float4 lfa = *(const float4*)&sL[kk * SLSTR + rl];
            float4 lfb = *(const float4*)&sL[kk * SLSTR + rl + 4];
            ulonglong2 uv = *(const ulonglong2*)&sU[kk * SUSTR + cl];
            ull l0 = splat2(lfa.x), l1 = splat2(lfa.y);
            ull l2 = splat2(lfa.z), l3 = splat2(lfa.w);
            ull l4 = splat2(lfb.x), l5 = splat2(lfb.y);
            ull l6 = splat2(lfb.z), l7 = splat2(lfb.w);
            ffma2(acc[0].x, l0, uv.x); ffma2(acc[0].y, l0, uv.y);
            ffma2(acc[1].x, l1, uv.x); ffma2(acc[1].y, l1, uv.y);
            ffma2(acc[2].x, l2, uv.x); ffma2(acc[2].y, l2, uv.y);
            ffma2(acc[3].x, l3, uv.x); ffma2(acc[3].y, l3, uv.y);
            ffma2(acc[4].x, l4, uv.x); ffma2(acc[4].y, l4, uv.y);
            ffma2(acc[5].x, l5, uv.x); ffma2(acc[5].y, l5, uv.y);
            ffma2(acc[6].x, l6, uv.x); ffma2(acc[6].y, l6, uv.y);
            ffma2(acc[7].x, l7, uv.x); ffma2(acc[7].y, l7, uv.y);
        }

#pragma unroll
        for (int i = 0; i < 8; i++) {
            if (r0 + i < NN)
                *(ulonglong2*)(A + (size_t)(r0 + i) * NN + c0) = acc[i];
        }
    }
}

// ============================================================================
// Kernel 5: finalize
// ============================================================================
__global__ void finalize_kernel(float* __restrict__ out) {
    int i = blockIdx.x * 256 + threadIdx.x;
    if (i < BB) {
        float ld = 0.0f, ld0 = 0.0f;
#pragma unroll
        for (int q = 0; q < NPAN; q++) {
            ld  += g_ldp[i * NPAN + q];
            ld0 += g_ldp[(NJOB - 1) * NPAN + q];
        }
        out[i] = g_logPr[i] + ld - ld0;
    }
}

extern "C" void kernel_launch(void* const* d_in, const int* in_sizes, int n_in,
                              void* d_out, int out_size) {
    const float* W   = (const float*)d_in[0];
    const float* lam = (const float*)d_in[1];
    const float* Vc  = (const float*)d_in[2];
    const int*   x   = (const int*)d_in[3];
    float* out = (float*)d_out;

    precompute_kernel<<<NN, NN>>>(W, lam, Vc);
    build_kernel<<<NJOB, 256>>>(x);

    cudaLaunchAttribute pdl[1];
    pdl[0].id = cudaLaunchAttributeProgrammaticStreamSerialization;
    pdl[0].val.programmaticStreamSerializationAllowed = 1;

    for (int p = 0; p < NPAN; p++) {
        {
            cudaLaunchConfig_t cfg = {};
            cfg.gridDim = dim3(NJOB, 1, 1);
            cfg.blockDim = dim3(256, 1, 1);
            cfg.attrs = pdl;
            cfg.numAttrs = 1;
            cfg.stream = 0;
            cudaLaunchKernelEx(&cfg, panel_kernel, p);
        }
        int ncols = NN - (p * NB + NB);
        if (ncols > 0) {
            int ntr = (ncols + 127) / 128;
            int ntc = (ncols + 63) / 64;
            cudaLaunchConfig_t cfg = {};
            cfg.gridDim = dim3(ntc, ntr, NJOB);
            cfg.blockDim = dim3(256, 1, 1);
            cfg.attrs = pdl;
            cfg.numAttrs = 1;
            cfg.stream = 0;
            cudaLaunchKernelEx(&cfg, gemm_kernel, p);
        }
    }
    finalize_kernel<<<4, 256>>>(out);
}